// round 13
// baseline (speedup 1.0000x reference)
#include <cuda_runtime.h>
#include <math.h>
#include <float.h>

#define NN 50000
#define EE 400000
#define DH 128
#define DE 32
#define NH 8
#define CH 16

typedef unsigned long long ull;

// ---------------- scratch (device globals: no allocation allowed) ----------------
__device__ float g_q[(size_t)NN * DH];
__device__ float g_k[(size_t)NN * DH];
__device__ float g_v[(size_t)NN * DH];
__device__ float g_agg[(size_t)NN * DH];        // skip projection per layer
__device__ float g_feat[(size_t)NN * DH];
__device__ float g_qwe[(size_t)NN * NH * DE];   // qWe[n][h][j] = sum_c q[n,hc]*We[hc][j]
__device__ float g_raw[(size_t)EE * NH];        // raw logits, CSR-PERMUTED order
// CSR (built once per call)
__device__ int g_deg[NN];
__device__ int g_fill[NN];
__device__ int g_rowptr[NN + 1];
__device__ int g_eperm[EE];                     // permuted pos -> original edge id

// ---------------- packed f32x2 helpers (2x fp32 FMA rate on sm_103a) -------------
__device__ __forceinline__ ull pk2(float lo, float hi) {
    ull r; asm("mov.b64 %0, {%1, %2};" : "=l"(r) : "f"(lo), "f"(hi)); return r;
}
__device__ __forceinline__ float2 upk2(ull a) {
    float2 r; asm("mov.b64 {%0, %1}, %2;" : "=f"(r.x), "=f"(r.y) : "l"(a)); return r;
}
__device__ __forceinline__ ull ffma2(ull a, ull b, ull c) {
    ull d; asm("fma.rn.f32x2 %0, %1, %2, %3;" : "=l"(d) : "l"(a), "l"(b), "l"(c)); return d;
}
__device__ __forceinline__ ull fadd2(ull a, ull b) {
    ull d; asm("add.rn.f32x2 %0, %1, %2;" : "=l"(d) : "l"(a), "l"(b)); return d;
}

// ---------------- fused 4-way node projection GEMM (unchanged, known-good) -------
#define BN 64
#define WPAD 132
#define PROJ_THREADS 256
#define PROJ_SMEM ((BN * DH + DH * WPAD) * 4)

__global__ void proj_kernel(const float* __restrict__ hin,
                            const float* __restrict__ Wq, const float* __restrict__ bq,
                            const float* __restrict__ Wk, const float* __restrict__ bk,
                            const float* __restrict__ Wv, const float* __restrict__ bv,
                            const float* __restrict__ Ws, const float* __restrict__ bs) {
    extern __shared__ float sh[];
    float* xs  = sh;             // [BN][DH]
    float* wsT = sh + BN * DH;   // [DH][WPAD]
    const int tid = threadIdx.x;
    const int node0 = blockIdx.x * BN;

    for (int i = tid; i < BN * DH / 4; i += PROJ_THREADS) {
        int n  = i / (DH / 4);
        int c4 = (i % (DH / 4)) * 4;
        float4 v = make_float4(0.f, 0.f, 0.f, 0.f);
        if (node0 + n < NN) v = *(const float4*)(hin + (size_t)(node0 + n) * DH + c4);
        *(float4*)(xs + n * DH + c4) = v;
    }

    const int cgrp = tid & 31;
    const int ngrp = tid >> 5;
    const int c0 = cgrp * 4;

    const float* Wlist[4] = {Wq, Wk, Wv, Ws};
    const float* Blist[4] = {bq, bk, bv, bs};
    float* Olist[4] = {g_q, g_k, g_v, g_agg};

    for (int w = 0; w < 4; ++w) {
        __syncthreads();
        const float* W = Wlist[w];
        for (int t = tid; t < DH * DH; t += PROJ_THREADS) {
            int ch = t >> 7, kk = t & (DH - 1);
            wsT[kk * WPAD + ch] = W[t];
        }
        __syncthreads();

        ull acc0[8], acc1[8];
#pragma unroll
        for (int i = 0; i < 8; ++i) { acc0[i] = 0ULL; acc1[i] = 0ULL; }

        const float* xrow = xs + (ngrp * 8) * DH;
#pragma unroll 8
        for (int kk = 0; kk < DH; ++kk) {
            ulonglong2 wp = *(const ulonglong2*)(wsT + kk * WPAD + c0);
#pragma unroll
            for (int i = 0; i < 8; ++i) {
                float xv = xrow[i * DH + kk];
                ull xx = pk2(xv, xv);
                acc0[i] = ffma2(xx, wp.x, acc0[i]);
                acc1[i] = ffma2(xx, wp.y, acc1[i]);
            }
        }

        float4 bias = *(const float4*)(Blist[w] + c0);
        float* O = Olist[w];
#pragma unroll
        for (int i = 0; i < 8; ++i) {
            int n = node0 + ngrp * 8 + i;
            if (n < NN) {
                float2 a = upk2(acc0[i]), b = upk2(acc1[i]);
                float4 o = make_float4(a.x + bias.x, a.y + bias.y, b.x + bias.z, b.y + bias.w);
                *(float4*)(O + (size_t)n * DH + c0) = o;
            }
        }
    }
}

// ---------------- qWe precompute: block per node, thread = (h, j) -----------------
__global__ void qwe_kernel(const float* __restrict__ We) {
    __shared__ float qs[DH];
    const int n = blockIdx.x;
    const int tid = threadIdx.x;
    if (tid < DH) qs[tid] = g_q[(size_t)n * DH + tid];
    __syncthreads();
    const int h = tid >> 5, j = tid & 31;
    float acc = 0.f;
#pragma unroll
    for (int c = 0; c < CH; ++c)
        acc += qs[h * CH + c] * We[(h * CH + c) * DE + j];   // coalesced in j
    g_qwe[((size_t)n * NH + h) * DE + j] = acc;
}

// ---------------- CSR build (once per call) ---------------------------------------
__global__ void csr_zero_kernel() {
    int i = blockIdx.x * blockDim.x + threadIdx.x;
    if (i < NN) { g_deg[i] = 0; g_fill[i] = 0; }
}
__global__ void csr_hist_kernel(const int* __restrict__ eidx) {
    int i = blockIdx.x * blockDim.x + threadIdx.x;
    if (i < EE) atomicAdd(&g_deg[eidx[EE + i]], 1);
}
__global__ void csr_scan_kernel() {
    __shared__ int sh[1024];
    __shared__ int carry;
    const int tid = threadIdx.x;
    if (tid == 0) carry = 0;
    __syncthreads();
    for (int base = 0; base < NN; base += 1024) {
        int v = (base + tid < NN) ? g_deg[base + tid] : 0;
        sh[tid] = v;
        __syncthreads();
        for (int off = 1; off < 1024; off <<= 1) {
            int t = (tid >= off) ? sh[tid - off] : 0;
            __syncthreads();
            sh[tid] += t;
            __syncthreads();
        }
        if (base + tid < NN) g_rowptr[base + tid] = carry + sh[tid] - v;
        __syncthreads();
        if (tid == 0) carry += sh[1023];
        __syncthreads();
    }
    if (tid == 0) g_rowptr[NN] = carry;   // == EE
}
__global__ void csr_scatter_kernel(const int* __restrict__ eidx) {
    int i = blockIdx.x * blockDim.x + threadIdx.x;
    if (i >= EE) return;
    int dst = eidx[EE + i];
    int pos = g_rowptr[dst] + atomicAdd(&g_fill[dst], 1);
    g_eperm[pos] = i;
}

// ---------------- pass A: logit = (q·k + qWe[dst]·ef[o]) / 4 ----------------------
// Permuted positions: raw written sequentially. No materialized e.
__global__ void edgeA_kernel(const int* __restrict__ eidx, const float* __restrict__ ef) {
    int gt = blockIdx.x * 256 + threadIdx.x;
    if (gt >= EE * NH) return;
    int p = gt >> 3, hh = gt & 7;
    int o = g_eperm[p];
    int src = eidx[o], dst = eidx[EE + o];

    const ulonglong2* qp = (const ulonglong2*)(g_q + (size_t)dst * DH + hh * CH);
    const ulonglong2* kp = (const ulonglong2*)(g_k + (size_t)src * DH + hh * CH);
    ull acc = 0ULL;
#pragma unroll
    for (int j = 0; j < 4; ++j) {           // 4 x 4 floats = CH = 16
        ulonglong2 q2 = qp[j], k2 = kp[j];
        acc = ffma2(q2.x, k2.x, acc);
        acc = ffma2(q2.y, k2.y, acc);
    }
    // qWe[dst,h] . ef[o]  (both contiguous 128B rows; 8 x 4 floats = DE = 32)
    const ulonglong2* wp = (const ulonglong2*)(g_qwe + ((size_t)dst * NH + hh) * DE);
    const ulonglong2* fp = (const ulonglong2*)(ef + (size_t)o * DE);
#pragma unroll
    for (int j = 0; j < 8; ++j) {           // FIXED: full 32 dims
        ulonglong2 w2 = wp[j], f2 = fp[j];
        acc = ffma2(w2.x, f2.x, acc);
        acc = ffma2(w2.y, f2.y, acc);
    }
    float2 r = upk2(acc);
    g_raw[gt] = (r.x + r.y) * 0.25f;   // / sqrt(C=16)
}

// ---------------- fused softmax + aggregate + edge-term GEMM + skip + GELU --------
// Warp per destination. agg = Σα·v + We·(Σα·ef) + skip.
__global__ void edgeC_kernel(const int* __restrict__ eidx, const float* __restrict__ ef,
                             const float* __restrict__ We, float* __restrict__ alpha_out,
                             float* __restrict__ outp, int apply_gelu) {
    const int gw = (blockIdx.x * 256 + threadIdx.x) >> 5;
    const int lane = threadIdx.x & 31;
    if (gw >= NN) return;
    const int d = gw;
    const int p0 = g_rowptr[d];
    const int deg = g_rowptr[d + 1] - p0;

    float4 acc = make_float4(0.f, 0.f, 0.f, 0.f);
    const int h2 = lane >> 2, q = lane & 3;
    float wef[8];                              // Σ α_{h2} * ef[j], j = q*8 .. q*8+8
#pragma unroll
    for (int t = 0; t < 8; ++t) wef[t] = 0.f;

    if (deg > 0) {
        int oL = -1, srcL = -1;
        if (lane < deg) { oL = g_eperm[p0 + lane]; srcL = eidx[oL]; }

        // ---- pass 1: online softmax stats (sequential raw reads) ----
        const int h = lane & 7, slot = lane >> 3;
        float m = -FLT_MAX, s = 0.f;
        for (int i = slot; i < deg; i += 4) {
            float r = g_raw[(size_t)(p0 + i) * NH + h];
            float nm = fmaxf(m, r);
            s = s * __expf(m - nm) + __expf(r - nm);
            m = nm;
        }
#pragma unroll
        for (int off = 8; off < 32; off <<= 1) {
            float mo = __shfl_xor_sync(0xffffffffu, m, off);
            float so = __shfl_xor_sync(0xffffffffu, s, off);
            float nm = fmaxf(m, mo);
            s = s * __expf(m - nm) + so * __expf(mo - nm);
            m = nm;
        }

        float mh = __shfl_sync(0xffffffffu, m, h2);
        float sh = __shfl_sync(0xffffffffu, s, h2);
        float inv = 1.f / (sh + 1e-16f);

        // ---- pass 2: acc_v = Σα·v ; wef = Σα·ef (per head, 8 dims/lane) ----
        for (int i = 0; i < deg; ++i) {
            int p = p0 + i;
            int o, src;
            if (i < 32) {
                o = __shfl_sync(0xffffffffu, oL, i);
                src = __shfl_sync(0xffffffffu, srcL, i);
            } else {
                o = g_eperm[p];
                src = eidx[o];
            }
            float r = g_raw[(size_t)p * NH + h2];
            float a = __expf(r - mh) * inv;
            float4 v4 = *(const float4*)(g_v + (size_t)src * DH + lane * 4);
            acc.x += v4.x * a;
            acc.y += v4.y * a;
            acc.z += v4.z * a;
            acc.w += v4.w * a;
            float4 f0 = *(const float4*)(ef + (size_t)o * DE + q * 8);
            float4 f1 = *(const float4*)(ef + (size_t)o * DE + q * 8 + 4);
            wef[0] += f0.x * a; wef[1] += f0.y * a; wef[2] += f0.z * a; wef[3] += f0.w * a;
            wef[4] += f1.x * a; wef[5] += f1.y * a; wef[6] += f1.z * a; wef[7] += f1.w * a;
            if (q == 0) alpha_out[(size_t)o * NH + h2] = a;
        }

        // ---- epilogue GEMM: acc[ch] += Σ_j We[ch][j] * wef_full[h2][j] ----
        // lane owns global channels lane*4..+4 (= head h2, sub q). wef_full is
        // distributed across the quad; fetch 8 j's at a time from quad member t.
        const int qbase = lane & ~3;
#pragma unroll
        for (int t = 0; t < 4; ++t) {
            float w0 = __shfl_sync(0xffffffffu, wef[0], qbase + t);
            float w1 = __shfl_sync(0xffffffffu, wef[1], qbase + t);
            float w2 = __shfl_sync(0xffffffffu, wef[2], qbase + t);
            float w3 = __shfl_sync(0xffffffffu, wef[3], qbase + t);
            float w4 = __shfl_sync(0xffffffffu, wef[4], qbase + t);
            float w5 = __shfl_sync(0xffffffffu, wef[5], qbase + t);
            float w6 = __shfl_sync(0xffffffffu, wef[6], qbase + t);
            float w7 = __shfl_sync(0xffffffffu, wef[7], qbase + t);
#pragma unroll
            for (int cc = 0; cc < 4; ++cc) {
                const float4* wr = (const float4*)(We + (size_t)(lane * 4 + cc) * DE + t * 8);
                float4 a0 = wr[0], a1 = wr[1];
                float sum = a0.x * w0 + a0.y * w1 + a0.z * w2 + a0.w * w3
                          + a1.x * w4 + a1.y * w5 + a1.z * w6 + a1.w * w7;
                if (cc == 0) acc.x += sum;
                else if (cc == 1) acc.y += sum;
                else if (cc == 2) acc.z += sum;
                else acc.w += sum;
            }
        }
    }

    // skip connection + optional exact-erf GELU, direct to layer output
    float4 skip = *(const float4*)(g_agg + (size_t)d * DH + lane * 4);
    acc.x += skip.x; acc.y += skip.y; acc.z += skip.z; acc.w += skip.w;
    if (apply_gelu) {
        acc.x *= normcdff(acc.x);
        acc.y *= normcdff(acc.y);
        acc.z *= normcdff(acc.z);
        acc.w *= normcdff(acc.w);
    }
    *(float4*)(outp + (size_t)d * DH + lane * 4) = acc;
}

// ---------------- launch ----------------------------------------------------------
extern "C" void kernel_launch(void* const* d_in, const int* in_sizes, int n_in,
                              void* d_out, int out_size) {
    const float* x   = (const float*)d_in[0];
    const float* ef  = (const float*)d_in[1];
    const float* Wq  = (const float*)d_in[2];
    const float* bq  = (const float*)d_in[3];
    const float* Wk  = (const float*)d_in[4];
    const float* bk  = (const float*)d_in[5];
    const float* Wv  = (const float*)d_in[6];
    const float* bv  = (const float*)d_in[7];
    const float* We  = (const float*)d_in[8];
    const float* Ws  = (const float*)d_in[9];
    const float* bs  = (const float*)d_in[10];
    const int* eidx  = (const int*)d_in[11];
    float* out = (float*)d_out;

    cudaFuncSetAttribute(proj_kernel, cudaFuncAttributeMaxDynamicSharedMemorySize, PROJ_SMEM);
    float* feat = nullptr;
    cudaGetSymbolAddress((void**)&feat, g_feat);

    const int nproj = (NN + BN - 1) / BN;

    // CSR build: once per call, reused by all 4 layers
    csr_zero_kernel<<<(NN + 255) / 256, 256>>>();
    csr_hist_kernel<<<(EE + 255) / 256, 256>>>(eidx);
    csr_scan_kernel<<<1, 1024>>>();
    csr_scatter_kernel<<<(EE + 255) / 256, 256>>>(eidx);

    for (int l = 0; l < 4; ++l) {
        const float* hin = (l == 0) ? x : feat;
        size_t off2 = (size_t)l * DH * DH;
        size_t offb = (size_t)l * DH;
        size_t offe = (size_t)l * DH * DE;

        proj_kernel<<<nproj, PROJ_THREADS, PROJ_SMEM>>>(hin,
            Wq + off2, bq + offb, Wk + off2, bk + offb,
            Wv + off2, bv + offb, Ws + off2, bs + offb);
        qwe_kernel<<<NN, 256>>>(We + offe);
        edgeA_kernel<<<(EE * NH) / 256, 256>>>(eidx, ef);
        edgeC_kernel<<<(NN * 32 + 255) / 256, 256>>>(eidx, ef, We + offe,
            out + (size_t)NN * DH + (size_t)l * EE * NH,
            (l == 3) ? out : feat, (l < 3) ? 1 : 0);
    }
}

// round 14
// speedup vs baseline: 1.1507x; 1.1507x over previous
#include <cuda_runtime.h>
#include <math.h>
#include <float.h>

#define NN 50000
#define EE 400000
#define DH 128
#define DE 32
#define NH 8
#define CH 16

typedef unsigned long long ull;

// ---------------- scratch (device globals: no allocation allowed) ----------------
__device__ float g_q[(size_t)NN * DH];
__device__ float g_k[(size_t)NN * DH];
__device__ float g_v[(size_t)NN * DH];
__device__ float g_agg[(size_t)NN * DH];        // skip projection per layer
__device__ float g_feat[(size_t)NN * DH];
__device__ float g_e[(size_t)EE * DH];          // materialized edge projection (orig order)
__device__ float g_raw[(size_t)EE * NH];        // raw logits (orig order)
// CSR (built once per call)
__device__ int g_deg[NN];
__device__ int g_fill[NN];
__device__ int g_rowptr[NN + 1];
__device__ int g_eperm[EE];

// ---------------- packed f32x2 helpers (2x fp32 FMA rate on sm_103a) -------------
__device__ __forceinline__ ull pk2(float lo, float hi) {
    ull r; asm("mov.b64 %0, {%1, %2};" : "=l"(r) : "f"(lo), "f"(hi)); return r;
}
__device__ __forceinline__ float2 upk2(ull a) {
    float2 r; asm("mov.b64 {%0, %1}, %2;" : "=f"(r.x), "=f"(r.y) : "l"(a)); return r;
}
__device__ __forceinline__ ull ffma2(ull a, ull b, ull c) {
    ull d; asm("fma.rn.f32x2 %0, %1, %2, %3;" : "=l"(d) : "l"(a), "l"(b), "l"(c)); return d;
}
__device__ __forceinline__ ull fadd2(ull a, ull b) {
    ull d; asm("add.rn.f32x2 %0, %1, %2;" : "=l"(d) : "l"(a), "l"(b)); return d;
}

// ---------------- fused 4-way node projection GEMM --------------------------------
#define BN 64
#define WPAD 132
#define PROJ_THREADS 256
#define PROJ_SMEM ((BN * DH + DH * WPAD) * 4)

__global__ void proj_kernel(const float* __restrict__ hin,
                            const float* __restrict__ Wq, const float* __restrict__ bq,
                            const float* __restrict__ Wk, const float* __restrict__ bk,
                            const float* __restrict__ Wv, const float* __restrict__ bv,
                            const float* __restrict__ Ws, const float* __restrict__ bs) {
    extern __shared__ float sh[];
    float* xs  = sh;             // [BN][DH]
    float* wsT = sh + BN * DH;   // [DH][WPAD]
    const int tid = threadIdx.x;
    const int node0 = blockIdx.x * BN;

    for (int i = tid; i < BN * DH / 4; i += PROJ_THREADS) {
        int n  = i / (DH / 4);
        int c4 = (i % (DH / 4)) * 4;
        float4 v = make_float4(0.f, 0.f, 0.f, 0.f);
        if (node0 + n < NN) v = *(const float4*)(hin + (size_t)(node0 + n) * DH + c4);
        *(float4*)(xs + n * DH + c4) = v;
    }

    const int cgrp = tid & 31;
    const int ngrp = tid >> 5;
    const int c0 = cgrp * 4;

    const float* Wlist[4] = {Wq, Wk, Wv, Ws};
    const float* Blist[4] = {bq, bk, bv, bs};
    float* Olist[4] = {g_q, g_k, g_v, g_agg};

    for (int w = 0; w < 4; ++w) {
        __syncthreads();
        const float* W = Wlist[w];
        for (int t = tid; t < DH * DH; t += PROJ_THREADS) {
            int ch = t >> 7, kk = t & (DH - 1);
            wsT[kk * WPAD + ch] = W[t];
        }
        __syncthreads();

        ull acc0[8], acc1[8];
#pragma unroll
        for (int i = 0; i < 8; ++i) { acc0[i] = 0ULL; acc1[i] = 0ULL; }

        const float* xrow = xs + (ngrp * 8) * DH;
#pragma unroll 4
        for (int kk4 = 0; kk4 < DH; kk4 += 4) {
            float4 xv[8];
#pragma unroll
            for (int i = 0; i < 8; ++i)
                xv[i] = *(const float4*)(xrow + i * DH + kk4);   // broadcast LDS.128
#pragma unroll
            for (int u = 0; u < 4; ++u) {
                ulonglong2 wp = *(const ulonglong2*)(wsT + (kk4 + u) * WPAD + c0);
#pragma unroll
                for (int i = 0; i < 8; ++i) {
                    float xs1 = (u == 0) ? xv[i].x : (u == 1) ? xv[i].y
                              : (u == 2) ? xv[i].z : xv[i].w;
                    ull xx = pk2(xs1, xs1);
                    acc0[i] = ffma2(xx, wp.x, acc0[i]);
                    acc1[i] = ffma2(xx, wp.y, acc1[i]);
                }
            }
        }

        float4 bias = *(const float4*)(Blist[w] + c0);
        float* O = Olist[w];
#pragma unroll
        for (int i = 0; i < 8; ++i) {
            int n = node0 + ngrp * 8 + i;
            if (n < NN) {
                float2 a = upk2(acc0[i]), b = upk2(acc1[i]);
                float4 o = make_float4(a.x + bias.x, a.y + bias.y, b.x + bias.z, b.y + bias.w);
                *(float4*)(O + (size_t)n * DH + c0) = o;
            }
        }
    }
}

// ---------------- edge projection GEMM: g_e = ef @ We^T  [E,32]x[32,128] ----------
#define EPB 64
__global__ void eproj_kernel(const float* __restrict__ We, const float* __restrict__ ef) {
    __shared__ float ws[DE][WPAD];      // ws[k][ch] = We[ch][k]
    __shared__ float efs[EPB][DE + 1];
    const int tid = threadIdx.x;
    const int e0 = blockIdx.x * EPB;

    for (int t = tid; t < DH * DE; t += 256) {
        int ch = t >> 5, k = t & (DE - 1);
        ws[k][ch] = We[t];
    }
    for (int t = tid; t < EPB * DE; t += 256) {
        efs[t >> 5][t & (DE - 1)] = ef[(size_t)e0 * DE + t];
    }
    __syncthreads();

    const int egrp = tid >> 5;
    const int cg = tid & 31;
    const int c0 = cg * 4;

    ull acc0[8], acc1[8];
#pragma unroll
    for (int i = 0; i < 8; ++i) { acc0[i] = 0ULL; acc1[i] = 0ULL; }

#pragma unroll
    for (int k = 0; k < DE; ++k) {
        ulonglong2 wp = *(const ulonglong2*)(&ws[k][c0]);
#pragma unroll
        for (int i = 0; i < 8; ++i) {
            float xv = efs[egrp * 8 + i][k];
            ull xx = pk2(xv, xv);
            acc0[i] = ffma2(xx, wp.x, acc0[i]);
            acc1[i] = ffma2(xx, wp.y, acc1[i]);
        }
    }

#pragma unroll
    for (int i = 0; i < 8; ++i) {
        int e = e0 + egrp * 8 + i;
        float2 a = upk2(acc0[i]), b = upk2(acc1[i]);
        *(float4*)(g_e + (size_t)e * DH + c0) = make_float4(a.x, a.y, b.x, b.y);
    }
}

// ---------------- CSR build (once per call) ---------------------------------------
__global__ void csr_zero_kernel() {
    int i = blockIdx.x * blockDim.x + threadIdx.x;
    if (i < NN) { g_deg[i] = 0; g_fill[i] = 0; }
}
__global__ void csr_hist_kernel(const int* __restrict__ eidx) {
    int i = blockIdx.x * blockDim.x + threadIdx.x;
    if (i < EE) atomicAdd(&g_deg[eidx[EE + i]], 1);
}
__global__ void csr_scan_kernel() {
    __shared__ int sh[1024];
    __shared__ int carry;
    const int tid = threadIdx.x;
    if (tid == 0) carry = 0;
    __syncthreads();
    for (int base = 0; base < NN; base += 1024) {
        int v = (base + tid < NN) ? g_deg[base + tid] : 0;
        sh[tid] = v;
        __syncthreads();
        for (int off = 1; off < 1024; off <<= 1) {
            int t = (tid >= off) ? sh[tid - off] : 0;
            __syncthreads();
            sh[tid] += t;
            __syncthreads();
        }
        if (base + tid < NN) g_rowptr[base + tid] = carry + sh[tid] - v;
        __syncthreads();
        if (tid == 0) carry += sh[1023];
        __syncthreads();
    }
    if (tid == 0) g_rowptr[NN] = carry;   // == EE
}
__global__ void csr_scatter_kernel(const int* __restrict__ eidx) {
    int i = blockIdx.x * blockDim.x + threadIdx.x;
    if (i >= EE) return;
    int dst = eidx[EE + i];
    int pos = g_rowptr[dst] + atomicAdd(&g_fill[dst], 1);
    g_eperm[pos] = i;
}

// ---------------- pass A: raw alpha (pure gather, no atomics) ---------------------
__global__ void edgeA_kernel(const int* __restrict__ eidx) {
    int gt = blockIdx.x * 256 + threadIdx.x;
    if (gt >= EE * NH) return;
    int e = gt >> 3, hh = gt & 7;
    int src = eidx[e], dst = eidx[EE + e];

    const ulonglong2* qp = (const ulonglong2*)(g_q + (size_t)dst * DH + hh * CH);
    const ulonglong2* kp = (const ulonglong2*)(g_k + (size_t)src * DH + hh * CH);
    const ulonglong2* ep = (const ulonglong2*)(g_e + (size_t)e   * DH + hh * CH);

    ull acc = 0ULL;
#pragma unroll
    for (int j = 0; j < 4; ++j) {
        ulonglong2 q2 = qp[j], k2 = kp[j], e2 = ep[j];
        acc = ffma2(q2.x, fadd2(k2.x, e2.x), acc);
        acc = ffma2(q2.y, fadd2(k2.y, e2.y), acc);
    }
    float2 r = upk2(acc);
    g_raw[gt] = (r.x + r.y) * 0.25f;   // / sqrt(C=16)
}

// ---------------- fused segment softmax + aggregate + skip + GELU -----------------
// Pass 1 lanes: h = lane&7, slot = lane>>3 — loop is UNIFORM in i0 (shfl legality)
// Pass 2 lanes: h2 = lane>>2, q = lane&3  — coalesced 512B row gathers, reg accum
__global__ void edgeC_kernel(const int* __restrict__ eidx, float* __restrict__ alpha_out,
                             float* __restrict__ outp, int apply_gelu) {
    const int gw = (blockIdx.x * 256 + threadIdx.x) >> 5;
    const int lane = threadIdx.x & 31;
    if (gw >= NN) return;
    const int d = gw;
    const int p0 = g_rowptr[d];
    const int deg = g_rowptr[d + 1] - p0;

    float4 acc = make_float4(0.f, 0.f, 0.f, 0.f);
    const int h2 = lane >> 2, q = lane & 3;

    if (deg > 0) {
        // warp-preload up to 32 edge ids + src ids
        int eL = -1, srcL = -1;
        if (lane < deg) { eL = g_eperm[p0 + lane]; srcL = eidx[eL]; }

        // ---- pass 1: online softmax stats (uniform trip count, shfl by all lanes) ----
        const int h = lane & 7, slot = lane >> 3;
        float m = -FLT_MAX, s = 0.f;
        for (int i0 = 0; i0 < deg; i0 += 4) {
            int i = i0 + slot;                 // may be >= deg for trailing lanes
            int ic = min(i, deg - 1);          // clamped: safe fetch index
            int e;
            if (i0 < 32) {                     // uniform predicate
                e = __shfl_sync(0xffffffffu, eL, ic);
            } else {                           // here deg-1 >= i0 >= 32
                e = g_eperm[p0 + ic];
            }
            if (i < deg) {
                float r = g_raw[(size_t)e * NH + h];
                float nm = fmaxf(m, r);
                s = s * __expf(m - nm) + __expf(r - nm);
                m = nm;
            }
        }
#pragma unroll
        for (int off = 8; off < 32; off <<= 1) {
            float mo = __shfl_xor_sync(0xffffffffu, m, off);
            float so = __shfl_xor_sync(0xffffffffu, s, off);
            float nm = fmaxf(m, mo);
            s = s * __expf(m - nm) + so * __expf(mo - nm);
            m = nm;
        }

        // redistribute stats to pass-2 lane layout
        float mh = __shfl_sync(0xffffffffu, m, h2);
        float sh = __shfl_sync(0xffffffffu, s, h2);
        float inv = 1.f / (sh + 1e-16f);

        // ---- pass 2: accumulate (v+e)*alpha (trip count uniform across warp) ----
        for (int i = 0; i < deg; ++i) {
            int e, src;
            if (i < 32) {
                e = __shfl_sync(0xffffffffu, eL, i);
                src = __shfl_sync(0xffffffffu, srcL, i);
            } else {
                e = g_eperm[p0 + i];
                src = eidx[e];
            }
            float r = g_raw[(size_t)e * NH + h2];
            float a = __expf(r - mh) * inv;
            float4 v4 = *(const float4*)(g_v + (size_t)src * DH + lane * 4);
            float4 e4 = *(const float4*)(g_e + (size_t)e   * DH + lane * 4);
            acc.x += (v4.x + e4.x) * a;
            acc.y += (v4.y + e4.y) * a;
            acc.z += (v4.z + e4.z) * a;
            acc.w += (v4.w + e4.w) * a;
            if (q == 0) alpha_out[(size_t)e * NH + h2] = a;
        }
    }

    // skip connection + optional exact-erf GELU, direct to layer output
    float4 skip = *(const float4*)(g_agg + (size_t)d * DH + lane * 4);
    acc.x += skip.x; acc.y += skip.y; acc.z += skip.z; acc.w += skip.w;
    if (apply_gelu) {
        acc.x *= normcdff(acc.x);
        acc.y *= normcdff(acc.y);
        acc.z *= normcdff(acc.z);
        acc.w *= normcdff(acc.w);
    }
    *(float4*)(outp + (size_t)d * DH + lane * 4) = acc;
}

// ---------------- launch ----------------------------------------------------------
extern "C" void kernel_launch(void* const* d_in, const int* in_sizes, int n_in,
                              void* d_out, int out_size) {
    const float* x   = (const float*)d_in[0];
    const float* ef  = (const float*)d_in[1];
    const float* Wq  = (const float*)d_in[2];
    const float* bq  = (const float*)d_in[3];
    const float* Wk  = (const float*)d_in[4];
    const float* bk  = (const float*)d_in[5];
    const float* Wv  = (const float*)d_in[6];
    const float* bv  = (const float*)d_in[7];
    const float* We  = (const float*)d_in[8];
    const float* Ws  = (const float*)d_in[9];
    const float* bs  = (const float*)d_in[10];
    const int* eidx  = (const int*)d_in[11];
    float* out = (float*)d_out;

    cudaFuncSetAttribute(proj_kernel, cudaFuncAttributeMaxDynamicSharedMemorySize, PROJ_SMEM);
    float* feat = nullptr;
    cudaGetSymbolAddress((void**)&feat, g_feat);

    const int nproj = (NN + BN - 1) / BN;

    // CSR build: once per call, reused by all 4 layers
    csr_zero_kernel<<<(NN + 255) / 256, 256>>>();
    csr_hist_kernel<<<(EE + 255) / 256, 256>>>(eidx);
    csr_scan_kernel<<<1, 1024>>>();
    csr_scatter_kernel<<<(EE + 255) / 256, 256>>>(eidx);

    for (int l = 0; l < 4; ++l) {
        const float* hin = (l == 0) ? x : feat;
        size_t off2 = (size_t)l * DH * DH;
        size_t offb = (size_t)l * DH;
        size_t offe = (size_t)l * DH * DE;

        proj_kernel<<<nproj, PROJ_THREADS, PROJ_SMEM>>>(hin,
            Wq + off2, bq + offb, Wk + off2, bk + offb,
            Wv + off2, bv + offb, Ws + off2, bs + offb);
        eproj_kernel<<<EE / EPB, 256>>>(We + offe, ef);
        edgeA_kernel<<<(EE * NH) / 256, 256>>>(eidx);
        edgeC_kernel<<<(NN * 32 + 255) / 256, 256>>>(eidx,
            out + (size_t)NN * DH + (size_t)l * EE * NH,
            (l == 3) ? out : feat, (l < 3) ? 1 : 0);
    }
}